// round 2
// baseline (speedup 1.0000x reference)
#include <cuda_runtime.h>

#define BN 8192
#define EN 8
#define HN 128
#define TS 128
#define NT (BN / TS)                 // 64 tiles per dim
#define NPAIRBLK (NT * (NT + 1) / 2) // 2080 upper-triangular tile pairs
#define KC 32                        // K-chunk width
#define QC (KC / 4)                  // float4 chunks per row per K-chunk

// ---------------- device scratch -------------------------------------------
__device__ __align__(16) float g_nrm[BN * HN];   // normalized embeddings (4 MB)
__device__ __align__(16) float g_p[BN * EN];     // softmax(routing_probs)
__device__ __align__(16) float g_lp[BN * EN];    // log_softmax(routing_probs)
__device__ float g_a[BN];                        // a[j] = sum_e p*logp
__device__ double g_usage[EN];
__device__ double g_task, g_eff, g_ent, g_kl;
__device__ unsigned long long g_cnt;

// ---------------- zero accumulators ----------------------------------------
__global__ void zero_kernel() {
    int t = threadIdx.x;
    if (t < EN) g_usage[t] = 0.0;
    else if (t == 8)  g_task = 0.0;
    else if (t == 9)  g_eff  = 0.0;
    else if (t == 10) g_ent  = 0.0;
    else if (t == 11) g_kl   = 0.0;
    else if (t == 12) g_cnt  = 0ull;
}

// ---------------- per-row preprocessing + cheap loss terms ------------------
__global__ __launch_bounds__(256) void prep_kernel(
    const float* __restrict__ logits,
    const int* __restrict__ targets,       // int32 (JAX canonicalizes int64->int32)
    const float* __restrict__ rp,
    const float* __restrict__ emb) {
    int warp = threadIdx.x >> 5, lane = threadIdx.x & 31;
    int row = blockIdx.x * 8 + warp;
    __shared__ float  s_us[EN];
    __shared__ double s_task[8], s_eff[8], s_ent[8];
    if (threadIdx.x < EN) s_us[threadIdx.x] = 0.f;
    __syncthreads();

    // normalize embedding row
    float4 v = *(const float4*)(emb + (size_t)row * HN + lane * 4);
    float ss = v.x * v.x + v.y * v.y + v.z * v.z + v.w * v.w;
#pragma unroll
    for (int o = 16; o > 0; o >>= 1) ss += __shfl_xor_sync(0xffffffffu, ss, o);
    float inv = rsqrtf(ss);
    float4 w = make_float4(v.x * inv, v.y * inv, v.z * inv, v.w * inv);
    *(float4*)(g_nrm + (size_t)row * HN + lane * 4) = w;

    // routing-prob softmax over E=8
    float r = (lane < EN) ? rp[row * EN + lane] : -3.0e38f;
    float m = r;
#pragma unroll
    for (int o = 4; o > 0; o >>= 1) m = fmaxf(m, __shfl_xor_sync(0xffffffffu, m, o));
    float ex = (lane < EN) ? expf(r - m) : 0.f;
    float es = ex;
#pragma unroll
    for (int o = 4; o > 0; o >>= 1) es += __shfl_xor_sync(0xffffffffu, es, o);
    float lse = m + logf(es);
    float lp = r - lse;
    float p  = expf(lp);
    if (lane < EN) { g_p[row * EN + lane] = p; g_lp[row * EN + lane] = lp; }

    float av  = (lane < EN) ? p * lp : 0.f;
    float evv = (lane < EN && r < 0.1f) ? r : 0.f;
    float nv  = (lane < EN) ? r * logf(r + 1e-8f) : 0.f;
#pragma unroll
    for (int o = 4; o > 0; o >>= 1) {
        av  += __shfl_xor_sync(0xffffffffu, av, o);
        evv += __shfl_xor_sync(0xffffffffu, evv, o);
        nv  += __shfl_xor_sync(0xffffffffu, nv, o);
    }
    if (lane < EN) atomicAdd(&s_us[lane], r);
    if (lane == 0) {
        g_a[row] = av;
        float l0 = logits[row * 3 + 0], l1 = logits[row * 3 + 1], l2 = logits[row * 3 + 2];
        float mm = fmaxf(l0, fmaxf(l1, l2));
        float lsm = mm + logf(expf(l0 - mm) + expf(l1 - mm) + expf(l2 - mm));
        int t = targets[row];
        float lt = (t == 0) ? l0 : ((t == 1) ? l1 : l2);
        s_task[warp] = (double)(lsm - lt);
        s_eff[warp]  = (double)evv;
        s_ent[warp]  = (double)nv;
    }
    __syncthreads();
    if (threadIdx.x == 0) {
        double a = 0, b = 0, c = 0;
        for (int i = 0; i < 8; i++) { a += s_task[i]; b += s_eff[i]; c += s_ent[i]; }
        atomicAdd(&g_task, a); atomicAdd(&g_eff, b); atomicAdd(&g_ent, c);
    }
    if (threadIdx.x < EN) atomicAdd(&g_usage[threadIdx.x], (double)s_us[threadIdx.x]);
}

// ---------------- fused sim-GEMM + masked-KL reduction ----------------------
// 128x128 block tiles (upper triangle), 16x16 threads, 8x8 micro-tiles.
// K processed in 32-wide chunks; shared tiles XOR-swizzled:
//   float4 chunk q (0..7) of row stored at column q ^ ((row>>3)&7).
// Epilogue p/logp stage ALIASES the GEMM tile buffer (union via byte buffer).
__global__ __launch_bounds__(256, 2) void pair_kernel() {
    __shared__ __align__(16) unsigned char s_buf[2 * TS * QC * 16]; // 32 KB
    float4* sAi = (float4*)s_buf;                // [TS][QC] swizzled
    float4* sAj = (float4*)(s_buf + TS * QC * 16);
    __shared__ float sIa[TS], sJa[TS];
    __shared__ float s_rk[8];
    __shared__ int   s_rc[8];

    // block -> (ti, tj), ti <= tj
    int ti = 0, rem = blockIdx.x;
    while (rem >= NT - ti) { rem -= NT - ti; ti++; }
    int tj = ti + rem;
    bool diag = (ti == tj);
    int ibase = ti * TS, jbase = tj * TS;

    int tid = threadIdx.x;
    if (tid < TS) { sIa[tid] = g_a[ibase + tid]; sJa[tid] = g_a[jbase + tid]; }

    int tx = tid & 15, ty = tid >> 4;
    int swA = ty & 7, swB = tx & 7;
    float acc[8][8] = {};

    for (int h = 0; h < HN / KC; h++) {          // 4 K-chunks of 32
        __syncthreads();                          // protect smem reuse across iters
        for (int idx = tid; idx < TS * QC; idx += 256) {
            int row = idx >> 3, q = idx & 7;
            int sw = (row >> 3) & 7;
            const float4* src =
                (const float4*)(g_nrm + (size_t)row * HN + h * KC + q * 4);
            sAi[row * QC + (q ^ sw)] = src[(size_t)ibase * (HN / 4) / 1 * 0 +
                                           ((size_t)ibase * HN) / 4];
            // (the line above is replaced below; see explicit addressing)
        }
        // explicit, simple addressing (overwrite of the placeholder above)
        for (int idx = tid; idx < TS * QC; idx += 256) {
            int row = idx >> 3, q = idx & 7;
            int sw = (row >> 3) & 7;
            sAi[row * QC + (q ^ sw)] =
                *(const float4*)(g_nrm + (size_t)(ibase + row) * HN + h * KC + q * 4);
            sAj[row * QC + (q ^ sw)] =
                *(const float4*)(g_nrm + (size_t)(jbase + row) * HN + h * KC + q * 4);
        }
        __syncthreads();
#pragma unroll
        for (int kc = 0; kc < QC; kc++) {
            float4 bvv[8];
#pragma unroll
            for (int c = 0; c < 8; c++) bvv[c] = sAj[(tx * 8 + c) * QC + (kc ^ swB)];
#pragma unroll
            for (int r = 0; r < 8; r++) {
                float4 av = sAi[(ty * 8 + r) * QC + (kc ^ swA)];
#pragma unroll
                for (int c = 0; c < 8; c++) {
                    acc[r][c] = fmaf(av.x, bvv[c].x, acc[r][c]);
                    acc[r][c] = fmaf(av.y, bvv[c].y, acc[r][c]);
                    acc[r][c] = fmaf(av.z, bvv[c].z, acc[r][c]);
                    acc[r][c] = fmaf(av.w, bvv[c].w, acc[r][c]);
                }
            }
        }
    }

    // ---- stage p / logp into the (now free) tile buffer ----
    __syncthreads();
    float* sPi  = (float*)s_buf;                  // [TS][EN] each = 4 KB
    float* sLPi = (float*)(s_buf + 4096);
    float* sPj  = (float*)(s_buf + 8192);
    float* sLPj = (float*)(s_buf + 12288);
    for (int idx = tid; idx < (TS * EN) / 4; idx += 256) {
        ((float4*)sPi)[idx]  = ((const float4*)(g_p  + ibase * EN))[idx];
        ((float4*)sLPi)[idx] = ((const float4*)(g_lp + ibase * EN))[idx];
        ((float4*)sPj)[idx]  = ((const float4*)(g_p  + jbase * EN))[idx];
        ((float4*)sLPj)[idx] = ((const float4*)(g_lp + jbase * EN))[idx];
    }
    __syncthreads();

    // ---- masked KL epilogue ----
    float kls = 0.f; int cnt = 0;
#pragma unroll
    for (int r = 0; r < 8; r++) {
        int il = ty * 8 + r;
        bool any = false;
#pragma unroll
        for (int c = 0; c < 8; c++) any |= (acc[r][c] > 0.8f);
        if (!any) continue;
        float pi[EN], lpi[EN];
#pragma unroll
        for (int e = 0; e < EN; e++) { pi[e] = sPi[il * EN + e]; lpi[e] = sLPi[il * EN + e]; }
        float ai = sIa[il];
#pragma unroll
        for (int c = 0; c < 8; c++) {
            if (acc[r][c] > 0.8f) {
                int jl = tx * 8 + c;
                if (diag) {
                    if (il != jl) {
                        float d = 0.f;
#pragma unroll
                        for (int e = 0; e < EN; e++) d = fmaf(lpi[e], sPj[jl * EN + e], d);
                        kls += sJa[jl] - d;
                        cnt += 1;
                    }
                } else {
                    float d1 = 0.f, d2 = 0.f;
#pragma unroll
                    for (int e = 0; e < EN; e++) {
                        d1 = fmaf(lpi[e], sPj[jl * EN + e], d1);
                        d2 = fmaf(sLPj[jl * EN + e], pi[e], d2);
                    }
                    kls += (ai + sJa[jl]) - (d1 + d2);
                    cnt += 2;
                }
            }
        }
    }
#pragma unroll
    for (int o = 16; o > 0; o >>= 1) {
        kls += __shfl_xor_sync(0xffffffffu, kls, o);
        cnt += __shfl_xor_sync(0xffffffffu, cnt, o);
    }
    int warp = tid >> 5, lane = tid & 31;
    if (lane == 0) { s_rk[warp] = kls; s_rc[warp] = cnt; }
    __syncthreads();
    if (tid == 0) {
        double K = 0; long long C = 0;
        for (int w = 0; w < 8; w++) { K += (double)s_rk[w]; C += s_rc[w]; }
        if (C) { atomicAdd(&g_kl, K); atomicAdd(&g_cnt, (unsigned long long)C); }
    }
}

// ---------------- final combine ---------------------------------------------
__global__ void final_kernel(const float* __restrict__ temperature,
                             float* __restrict__ out) {
    double u[EN], mu = 0.0;
    for (int e = 0; e < EN; e++) { u[e] = g_usage[e] / (double)BN; mu += u[e]; }
    mu /= (double)EN;
    double var = 0.0;
    for (int e = 0; e < EN; e++) var += (u[e] - mu) * (u[e] - mu);
    var /= (double)(EN - 1);
    double cons = (g_cnt > 0) ? 0.1 * (g_kl / (double)g_cnt) : 0.0;
    double t = (double)temperature[0] - 1.0;
    double loss = g_task / (double)BN
                + 0.1 * var * (double)(EN * EN)
                + 0.05 * g_eff / (double)BN
                + cons
                + 0.01 * g_ent / (double)BN
                + 0.01 * t * t;
    out[0] = (float)loss;
}

// ---------------- launch -----------------------------------------------------
extern "C" void kernel_launch(void* const* d_in, const int* in_sizes, int n_in,
                              void* d_out, int out_size) {
    const float* logits  = (const float*)d_in[0];
    const int*   targets = (const int*)d_in[1];
    const float* rp      = (const float*)d_in[2];
    const float* emb     = (const float*)d_in[3];
    const float* temp    = (const float*)d_in[4];
    float* out = (float*)d_out;

    zero_kernel<<<1, 32>>>();
    prep_kernel<<<BN / 8, 256>>>(logits, targets, rp, emb);
    pair_kernel<<<NPAIRBLK, 256>>>();
    final_kernel<<<1, 1>>>(temp, out);
}

// round 5
// speedup vs baseline: 3.0559x; 3.0559x over previous
#include <cuda_runtime.h>
#include <cuda_bf16.h>

#define BN 8192
#define EN 8
#define HN 128
#define TS 128
#define NT (BN / TS)                 // 64 tiles per dim
#define NPAIR (NT * (NT + 1) / 2)    // 2080 upper-triangular tile pairs
#define GRID_PAIR 296                // 2 CTAs/SM, one wave

// ---------------- device scratch -------------------------------------------
// bf16 tile images, pre-swizzled SW128-style, K split in halves of 64:
// g_tiles[h][tile][row*128 + swz(col2*2)], 2 MB total, L2-resident.
__device__ __align__(1024) unsigned char g_tiles[2][NT][TS * 128];
__device__ __align__(16) float g_p[BN * EN];
__device__ __align__(16) float g_lp[BN * EN];
__device__ float g_a[BN];
__device__ double g_usage[EN];
__device__ double g_task, g_eff, g_ent, g_kl;
__device__ unsigned long long g_cnt;

// ---------------- PTX helpers ----------------------------------------------
__device__ __forceinline__ unsigned smem_u32(const void* p) {
    unsigned a;
    asm("{ .reg .u64 t; cvta.to.shared.u64 t, %1; cvt.u32.u64 %0, t; }"
        : "=r"(a) : "l"(p));
    return a;
}
__device__ __forceinline__ void ldsm4(unsigned* r, unsigned addr) {
    asm volatile("ldmatrix.sync.aligned.m8n8.x4.shared.b16 {%0,%1,%2,%3}, [%4];"
                 : "=r"(r[0]), "=r"(r[1]), "=r"(r[2]), "=r"(r[3]) : "r"(addr));
}
__device__ __forceinline__ void mma16816(float* d, const unsigned* a, const unsigned* b) {
    asm volatile(
        "mma.sync.aligned.m16n8k16.row.col.f32.bf16.bf16.f32 "
        "{%0,%1,%2,%3}, {%4,%5,%6,%7}, {%8,%9}, {%0,%1,%2,%3};"
        : "+f"(d[0]), "+f"(d[1]), "+f"(d[2]), "+f"(d[3])
        : "r"(a[0]), "r"(a[1]), "r"(a[2]), "r"(a[3]), "r"(b[0]), "r"(b[1]));
}

// ---------------- zero accumulators ----------------------------------------
__global__ void zero_kernel() {
    int t = threadIdx.x;
    if (t < EN) g_usage[t] = 0.0;
    else if (t == 8)  g_task = 0.0;
    else if (t == 9)  g_eff  = 0.0;
    else if (t == 10) g_ent  = 0.0;
    else if (t == 11) g_kl   = 0.0;
    else if (t == 12) g_cnt  = 0ull;
}

// ---------------- per-row preprocessing + cheap loss terms ------------------
__global__ __launch_bounds__(256) void prep_kernel(
    const float* __restrict__ logits,
    const int* __restrict__ targets,
    const float* __restrict__ rp,
    const float* __restrict__ emb) {
    int warp = threadIdx.x >> 5, lane = threadIdx.x & 31;
    int row = blockIdx.x * 8 + warp;
    __shared__ float  s_us[EN];
    __shared__ double s_task[8], s_eff[8], s_ent[8];
    if (threadIdx.x < EN) s_us[threadIdx.x] = 0.f;
    __syncthreads();

    // normalize embedding row (float4 per lane = 4 consecutive cols)
    float4 v = *(const float4*)(emb + (size_t)row * HN + lane * 4);
    float ss = v.x * v.x + v.y * v.y + v.z * v.z + v.w * v.w;
#pragma unroll
    for (int o = 16; o > 0; o >>= 1) ss += __shfl_xor_sync(0xffffffffu, ss, o);
    float inv = rsqrtf(ss);
    float4 w = make_float4(v.x * inv, v.y * inv, v.z * inv, v.w * inv);

    // store bf16 pre-swizzled tile image: half = lane>>4, cols (lane*4)&63..+3
    {
        int hh  = lane >> 4;
        int c2  = (lane * 4) & 63;
        unsigned b0 = (unsigned)((row & (TS - 1)) * 128 + c2 * 2);
        unsigned sw = b0 ^ ((b0 >> 3) & 0x70);
        unsigned u0 = __bfloat16_as_ushort(__float2bfloat16_rn(w.x));
        unsigned u1 = __bfloat16_as_ushort(__float2bfloat16_rn(w.y));
        unsigned u2 = __bfloat16_as_ushort(__float2bfloat16_rn(w.z));
        unsigned u3 = __bfloat16_as_ushort(__float2bfloat16_rn(w.w));
        uint2 val = make_uint2(u0 | (u1 << 16), u2 | (u3 << 16));
        *(uint2*)(&g_tiles[hh][row >> 7][sw]) = val;
    }

    // routing-prob softmax over E=8
    float r = (lane < EN) ? rp[row * EN + lane] : -3.0e38f;
    float m = r;
#pragma unroll
    for (int o = 4; o > 0; o >>= 1) m = fmaxf(m, __shfl_xor_sync(0xffffffffu, m, o));
    float ex = (lane < EN) ? expf(r - m) : 0.f;
    float es = ex;
#pragma unroll
    for (int o = 4; o > 0; o >>= 1) es += __shfl_xor_sync(0xffffffffu, es, o);
    float lse = m + logf(es);
    float lp = r - lse;
    float p  = expf(lp);
    if (lane < EN) { g_p[row * EN + lane] = p; g_lp[row * EN + lane] = lp; }

    float av  = (lane < EN) ? p * lp : 0.f;
    float evv = (lane < EN && r < 0.1f) ? r : 0.f;
    float nv  = (lane < EN) ? r * logf(r + 1e-8f) : 0.f;
#pragma unroll
    for (int o = 4; o > 0; o >>= 1) {
        av  += __shfl_xor_sync(0xffffffffu, av, o);
        evv += __shfl_xor_sync(0xffffffffu, evv, o);
        nv  += __shfl_xor_sync(0xffffffffu, nv, o);
    }
    if (lane < EN) atomicAdd(&s_us[lane], r);
    if (lane == 0) {
        g_a[row] = av;
        float l0 = logits[row * 3 + 0], l1 = logits[row * 3 + 1], l2 = logits[row * 3 + 2];
        float mm = fmaxf(l0, fmaxf(l1, l2));
        float lsm = mm + logf(expf(l0 - mm) + expf(l1 - mm) + expf(l2 - mm));
        int t = targets[row];
        float lt = (t == 0) ? l0 : ((t == 1) ? l1 : l2);
        s_task[warp] = (double)(lsm - lt);
        s_eff[warp]  = (double)evv;
        s_ent[warp]  = (double)nv;
    }
    __syncthreads();
    if (threadIdx.x == 0) {
        double a = 0, b = 0, c = 0;
        for (int i = 0; i < 8; i++) { a += s_task[i]; b += s_eff[i]; c += s_ent[i]; }
        atomicAdd(&g_task, a); atomicAdd(&g_eff, b); atomicAdd(&g_ent, c);
    }
    if (threadIdx.x < EN) atomicAdd(&g_usage[threadIdx.x], (double)s_us[threadIdx.x]);
}

// ---------------- HMMA pair kernel ------------------------------------------
// Persistent 296 CTAs. Per tile-pair: two K-halves; per half: linear copy of
// pre-swizzled bf16 tiles to smem, then ldmatrix + mma.sync m16n8k16 loop.
// Warp w: m-rows (w&3)*32..+32, n-cols (w>>2)*64..+64 -> acc[2][8][4] fp32.
// Epilogue: p/logp/a staged into smem aliasing sA/sB, threshold + masked KL.
__global__ __launch_bounds__(256, 2) void pair_kernel() {
    __shared__ __align__(1024) unsigned char sA[TS * 128];  // 16 KB
    __shared__ __align__(1024) unsigned char sB[TS * 128];  // 16 KB
    __shared__ float s_rk[8];
    __shared__ int   s_rc[8];

    // epilogue aliases (valid only after GEMM of current tile is done)
    float* sPi  = (float*)sA;                 // [TS][EN] 4 KB
    float* sLPi = (float*)(sA + 4096);
    float* sPj  = (float*)(sA + 8192);
    float* sLPj = (float*)(sA + 12288);
    float* sIa  = (float*)sB;                 // [TS] 512 B
    float* sJa  = (float*)(sB + 512);

    int tid  = threadIdx.x;
    int wid  = tid >> 5;
    int lane = tid & 31;

    unsigned sAu = smem_u32(sA);
    unsigned sBu = smem_u32(sB);

    int mbase = (wid & 3) * 32;     // warp's m-row base (i side)
    int nbase = (wid >> 2) * 64;    // warp's n-col base (j side)

    // ---- precompute per-lane ldmatrix row addressing ----
    // A (x4): m0 rows0-7 klo, m1 rows8-15 klo, m2 rows0-7 khi, m3 rows8-15 khi
    int rowA  = ((lane >> 3) & 1) * 8 + (lane & 7);
    int qselA = lane >> 4;              // 0=klo, 1=khi
    // B (x4): m0 nt_even rows klo, m1 khi, m2 nt_odd rows klo, m3 khi
    int rowB  = ((lane >> 4) & 1) * 8 + (lane & 7);
    int qselB = (lane >> 3) & 1;

    float kls = 0.f;
    int   cnt = 0;

    for (int t = blockIdx.x; t < NPAIR; t += GRID_PAIR) {
        int ti = 0, rem = t;
        while (rem >= NT - ti) { rem -= NT - ti; ti++; }
        int tj = ti + rem;
        bool diag = (ti == tj);
        int ibase = ti * TS, jbase = tj * TS;

        float acc[2][8][4];
#pragma unroll
        for (int a = 0; a < 2; a++)
#pragma unroll
            for (int b = 0; b < 8; b++)
#pragma unroll
                for (int c = 0; c < 4; c++) acc[a][b][c] = 0.f;

        for (int h = 0; h < 2; h++) {
            __syncthreads();   // prior reads of sA/sB (mma or epilogue) done
            const uint4* srcA = (const uint4*)g_tiles[h][ti];
            const uint4* srcB = (const uint4*)g_tiles[h][tj];
#pragma unroll
            for (int k = 0; k < 4; k++) {
                int idx = tid + k * 256;
                ((uint4*)sA)[idx] = srcA[idx];
                ((uint4*)sB)[idx] = srcB[idx];
            }
            __syncthreads();

#pragma unroll
            for (int s = 0; s < 4; s++) {          // 4 k16-steps per half
                unsigned af[2][4], bf[4][4];
#pragma unroll
                for (int mt = 0; mt < 2; mt++) {
                    int r = mbase + mt * 16 + rowA;
                    int q = s * 2 + qselA;
                    ldsm4(af[mt], sAu + r * 128 + (((q ^ (r & 7)) << 4)));
                }
#pragma unroll
                for (int pnt = 0; pnt < 4; pnt++) { // n-tile pairs
                    int r = nbase + pnt * 16 + rowB;
                    int q = s * 2 + qselB;
                    ldsm4(bf[pnt], sBu + r * 128 + (((q ^ (r & 7)) << 4)));
                }
#pragma unroll
                for (int mt = 0; mt < 2; mt++)
#pragma unroll
                    for (int pnt = 0; pnt < 4; pnt++) {
                        mma16816(acc[mt][pnt * 2 + 0], af[mt], &bf[pnt][0]);
                        mma16816(acc[mt][pnt * 2 + 1], af[mt], &bf[pnt][2]);
                    }
            }
        }

        // ---- stage p / logp / a into aliased smem ----
        __syncthreads();
        for (int idx = tid; idx < (TS * EN) / 4; idx += 256) {
            ((float4*)sPi)[idx]  = ((const float4*)(g_p  + ibase * EN))[idx];
            ((float4*)sLPi)[idx] = ((const float4*)(g_lp + ibase * EN))[idx];
            ((float4*)sPj)[idx]  = ((const float4*)(g_p  + jbase * EN))[idx];
            ((float4*)sLPj)[idx] = ((const float4*)(g_lp + jbase * EN))[idx];
        }
        if (tid < TS) { sIa[tid] = g_a[ibase + tid]; sJa[tid] = g_a[jbase + tid]; }
        __syncthreads();

        // ---- masked KL epilogue (D-fragment layout) ----
#pragma unroll
        for (int mt = 0; mt < 2; mt++) {
#pragma unroll
            for (int hf = 0; hf < 2; hf++) {
                int il = mbase + mt * 16 + hf * 8 + (lane >> 2);
                float4 pi0  = *(const float4*)(sPi  + il * EN);
                float4 pi1  = *(const float4*)(sPi  + il * EN + 4);
                float4 lpi0 = *(const float4*)(sLPi + il * EN);
                float4 lpi1 = *(const float4*)(sLPi + il * EN + 4);
                float  a_i  = sIa[il];
#pragma unroll
                for (int nt = 0; nt < 8; nt++) {
                    float v0 = acc[mt][nt][hf * 2 + 0];
                    float v1 = acc[mt][nt][hf * 2 + 1];
                    if (!(v0 > 0.8f) && !(v1 > 0.8f)) continue;
                    int jl0 = nbase + nt * 8 + (lane & 3) * 2;
#pragma unroll
                    for (int cc = 0; cc < 2; cc++) {
                        float f = (cc == 0) ? v0 : v1;
                        int jl = jl0 + cc;
                        if (f > 0.8f && !(diag && il == jl)) {
                            float4 pj0 = *(const float4*)(sPj + jl * EN);
                            float4 pj1 = *(const float4*)(sPj + jl * EN + 4);
                            float d1 = lpi0.x * pj0.x + lpi0.y * pj0.y +
                                       lpi0.z * pj0.z + lpi0.w * pj0.w +
                                       lpi1.x * pj1.x + lpi1.y * pj1.y +
                                       lpi1.z * pj1.z + lpi1.w * pj1.w;
                            float kl1 = sJa[jl] - d1;
                            if (diag) {
                                kls += kl1; cnt += 1;       // ordered pair, once
                            } else {
                                float4 lpj0 = *(const float4*)(sLPj + jl * EN);
                                float4 lpj1 = *(const float4*)(sLPj + jl * EN + 4);
                                float d2 = lpj0.x * pi0.x + lpj0.y * pi0.y +
                                           lpj0.z * pi0.z + lpj0.w * pi0.w +
                                           lpj1.x * pi1.x + lpj1.y * pi1.y +
                                           lpj1.z * pi1.z + lpj1.w * pi1.w;
                                kls += kl1 + (a_i - d2); cnt += 2;
                            }
                        }
                    }
                }
            }
        }
    }

    // ---- flush per-thread accumulators ----
#pragma unroll
    for (int o = 16; o > 0; o >>= 1) {
        kls += __shfl_xor_sync(0xffffffffu, kls, o);
        cnt += __shfl_xor_sync(0xffffffffu, cnt, o);
    }
    if (lane == 0) { s_rk[wid] = kls; s_rc[wid] = cnt; }
    __syncthreads();
    if (tid == 0) {
        double K = 0; long long C = 0;
        for (int w = 0; w < 8; w++) { K += (double)s_rk[w]; C += s_rc[w]; }
        if (C) { atomicAdd(&g_kl, K); atomicAdd(&g_cnt, (unsigned long long)C); }
    }
}

// ---------------- final combine ---------------------------------------------
__global__ void final_kernel(const float* __restrict__ temperature,
                             float* __restrict__ out) {
    double u[EN], mu = 0.0;
    for (int e = 0; e < EN; e++) { u[e] = g_usage[e] / (double)BN; mu += u[e]; }
    mu /= (double)EN;
    double var = 0.0;
    for (int e = 0; e < EN; e++) var += (u[e] - mu) * (u[e] - mu);
    var /= (double)(EN - 1);
    double cons = (g_cnt > 0) ? 0.1 * (g_kl / (double)g_cnt) : 0.0;
    double t = (double)temperature[0] - 1.0;
    double loss = g_task / (double)BN
                + 0.1 * var * (double)(EN * EN)
                + 0.05 * g_eff / (double)BN
                + cons
                + 0.01 * g_ent / (double)BN
                + 0.01 * t * t;
    out[0] = (float)loss;
}

// ---------------- launch -----------------------------------------------------
extern "C" void kernel_launch(void* const* d_in, const int* in_sizes, int n_in,
                              void* d_out, int out_size) {
    const float* logits  = (const float*)d_in[0];
    const int*   targets = (const int*)d_in[1];
    const float* rp      = (const float*)d_in[2];
    const float* emb     = (const float*)d_in[3];
    const float* temp    = (const float*)d_in[4];
    float* out = (float*)d_out;

    zero_kernel<<<1, 32>>>();
    prep_kernel<<<BN / 8, 256>>>(logits, targets, rp, emb);
    pair_kernel<<<GRID_PAIR, 256>>>();
    final_kernel<<<1, 1>>>(temp, out);
}